// round 1
// baseline (speedup 1.0000x reference)
#include <cuda_runtime.h>
#include <math.h>
#include <stdint.h>

// Problem-size maxima (B=8, N=R*R=4096, M=4096 in this dataset).
#define MAXB 8
#define MAXN 4096
#define MAXM 4096

// Chamfer tiling
#define TB    128          // threads per block
#define NP    4            // n-points per thread
#define NTILE (TB * NP)    // 512 n-points per block
#define MCH   512          // m-chunk per block

// Scratch (no cudaMalloc allowed)
__device__ float4 g_pred[MAXB * MAXN];     // (px,py,pz, ||p||^2)
__device__ int    g_min_i[MAXB * MAXN];    // float bits, int-ordered (all >= 0)

// ---------------------------------------------------------------------------
// Kernel A: camera math -> predicted world points; init mins to +inf
// ---------------------------------------------------------------------------
__global__ void pred_kernel(const float* __restrict__ c,
                            const float* __restrict__ depth,
                            int B, int N, int R)
{
    int idx = blockIdx.x * blockDim.x + threadIdx.x;
    if (idx >= B * N) return;
    int b = idx / N;
    int n = idx - b * N;

    const float* cb = c + b * 25;
    // cam2world row-major 4x4 in cb[0..15]; intrinsics 3x3 in cb[16..24]
    float m00 = cb[0],  m01 = cb[1],  m02 = cb[2],  m03 = cb[3];
    float m10 = cb[4],  m11 = cb[5],  m12 = cb[6],  m13 = cb[7];
    float m20 = cb[8],  m21 = cb[9],  m22 = cb[10], m23 = cb[11];
    float fx  = cb[16], sk = cb[17],  cx  = cb[18];
    float fy  = cb[20], cy = cb[21];

    int i = n / R;
    int j = n - i * R;
    float x_cam = (j + 0.5f) / (float)R;   // gj -> column index
    float y_cam = (i + 0.5f) / (float)R;   // gi -> row index

    float x_lift = (x_cam - cx + cy * sk / fy - sk * y_cam / fy) / fx;
    float y_lift = (y_cam - cy) / fy;

    // world = cam2world @ [x_lift, y_lift, 1, 1] (first 3 rows)
    float wx = m00 * x_lift + m01 * y_lift + m02 + m03;
    float wy = m10 * x_lift + m11 * y_lift + m12 + m13;
    float wz = m20 * x_lift + m21 * y_lift + m22 + m23;

    float ox = m03, oy = m13, oz = m23;
    float dx = wx - ox, dy = wy - oy, dz = wz - oz;
    float invn = 1.0f / sqrtf(dx * dx + dy * dy + dz * dz);

    float dep = depth[idx];
    float s = dep * invn;
    float px = fmaf(s, dx, ox);
    float py = fmaf(s, dy, oy);
    float pz = fmaf(s, dz, oz);

    float pn = px * px + py * py + pz * pz;
    g_pred[idx]  = make_float4(px, py, pz, pn);
    g_min_i[idx] = 0x7f800000;  // +inf
}

// ---------------------------------------------------------------------------
// Kernel B: chamfer min over pc. d0[n] = pn + min_m (qm - 2*dot(p,q))
// grid: (M/MCH, N/NTILE, B)
// ---------------------------------------------------------------------------
__global__ void __launch_bounds__(TB)
chamfer_kernel(const float* __restrict__ pc, int B, int N, int M)
{
    __shared__ float4 sq[MCH];

    int b      = blockIdx.z;
    int ntile  = blockIdx.y;
    int m0     = blockIdx.x * MCH;

    // Stage m-chunk into shared as (qx,qy,qz, ||q||^2)
    const float* pcb = pc + (size_t)b * M * 3;
    for (int m = threadIdx.x; m < MCH; m += TB) {
        int mg = m0 + m;
        if (mg < M) {
            float qx = pcb[mg * 3 + 0];
            float qy = pcb[mg * 3 + 1];
            float qz = pcb[mg * 3 + 2];
            sq[m] = make_float4(qx, qy, qz, qx * qx + qy * qy + qz * qz);
        } else {
            sq[m] = make_float4(0.f, 0.f, 0.f, 1e30f);
        }
    }
    __syncthreads();

    // Register tile of NP predicted points
    float px[NP], py[NP], pz[NP], pn[NP], mn[NP];
    int nbase = ntile * NTILE + threadIdx.x;
    #pragma unroll
    for (int p = 0; p < NP; p++) {
        int ng = nbase + p * TB;
        float4 v = (ng < N) ? g_pred[b * N + ng] : make_float4(0.f, 0.f, 0.f, 0.f);
        px[p] = v.x; py[p] = v.y; pz[p] = v.z; pn[p] = v.w;
        mn[p] = INFINITY;
    }

    // Sweep the chunk: per pair 1 FMUL + 3 FFMA + 1 FMNMX
    #pragma unroll 4
    for (int m = 0; m < MCH; m++) {
        float4 q = sq[m];
        #pragma unroll
        for (int p = 0; p < NP; p++) {
            float dot = px[p] * q.x;
            dot = fmaf(py[p], q.y, dot);
            dot = fmaf(pz[p], q.z, dot);
            float t = fmaf(-2.0f, dot, q.w);
            mn[p] = fminf(mn[p], t);
        }
    }

    // Publish: clamp >= 0 so int-ordered atomicMin is valid
    #pragma unroll
    for (int p = 0; p < NP; p++) {
        int ng = nbase + p * TB;
        if (ng < N) {
            float v = fmaxf(pn[p] + mn[p], 0.0f);
            atomicMin(&g_min_i[b * N + ng], __float_as_int(v));
        }
    }
}

// ---------------------------------------------------------------------------
// Kernel C: per batch, bitonic-sort the N mins in shared, mean of smallest K,
// out[b] = 2 * mean
// ---------------------------------------------------------------------------
__global__ void __launch_bounds__(1024)
reduce_kernel(float* __restrict__ out, int B, int N, int K)
{
    __shared__ float s[MAXN];
    __shared__ float red[32];
    int b = blockIdx.x;

    for (int i = threadIdx.x; i < N; i += blockDim.x)
        s[i] = __int_as_float(g_min_i[b * N + i]);
    __syncthreads();

    // Bitonic sort ascending (N power of 2)
    for (int k = 2; k <= N; k <<= 1) {
        for (int j = k >> 1; j > 0; j >>= 1) {
            for (int t = threadIdx.x; t < N; t += blockDim.x) {
                int ixj = t ^ j;
                if (ixj > t) {
                    bool up = ((t & k) == 0);
                    float a = s[t], c2 = s[ixj];
                    bool swap = up ? (a > c2) : (a < c2);
                    if (swap) { s[t] = c2; s[ixj] = a; }
                }
            }
            __syncthreads();
        }
    }

    // Sum first K
    float acc = 0.0f;
    for (int i = threadIdx.x; i < K; i += blockDim.x)
        acc += s[i];
    // warp reduce
    for (int off = 16; off > 0; off >>= 1)
        acc += __shfl_down_sync(0xffffffffu, acc, off);
    int wid = threadIdx.x >> 5;
    int lid = threadIdx.x & 31;
    if (lid == 0) red[wid] = acc;
    __syncthreads();
    if (wid == 0) {
        int nw = (blockDim.x + 31) >> 5;
        float v = (lid < nw) ? red[lid] : 0.0f;
        for (int off = 16; off > 0; off >>= 1)
            v += __shfl_down_sync(0xffffffffu, v, off);
        if (lid == 0)
            out[b] = 2.0f * v / (float)K;
    }
}

// ---------------------------------------------------------------------------
extern "C" void kernel_launch(void* const* d_in, const int* in_sizes, int n_in,
                              void* d_out, int out_size)
{
    const float* c     = (const float*)d_in[0];
    const float* depth = (const float*)d_in[1];
    const float* pc    = (const float*)d_in[2];
    // d_in[3] = resolution scalar (device); derive shapes from sizes instead.

    int B = in_sizes[0] / 25;
    int N = in_sizes[1] / B;
    int M = in_sizes[2] / (B * 3);
    int R = 1;
    while (R * R < N) R++;

    float* out = (float*)d_out;

    int total = B * N;
    pred_kernel<<<(total + 255) / 256, 256>>>(c, depth, B, N, R);

    dim3 grid((M + MCH - 1) / MCH, (N + NTILE - 1) / NTILE, B);
    chamfer_kernel<<<grid, TB>>>(pc, B, N, M);

    int K = (N < M ? N : M) / 2;
    reduce_kernel<<<B, 1024>>>(out, B, N, K);
}

// round 2
// speedup vs baseline: 1.9659x; 1.9659x over previous
#include <cuda_runtime.h>
#include <math.h>
#include <stdint.h>

#define MAXB 8
#define MAXN 4096
#define MAXM 4096

// Chamfer tiling
#define TB    128          // threads per block
#define NV    8            // n-points per thread (4 packed f32x2 pairs)
#define NTILE (TB * NV)    // 1024 n-points per block
#define MCH   256          // m-chunk per block

// Scratch (no cudaMalloc allowed)
__device__ float4 g_pred[MAXB * MAXN];     // (px,py,pz, ||p||^2)
__device__ int    g_min_i[MAXB * MAXN];    // float bits, int-ordered (all >= 0)

#define F32X2_MUL(d, a, b) \
    asm("mul.rn.f32x2 %0, %1, %2;" : "=l"(d) : "l"(a), "l"(b))
#define F32X2_FMA(d, a, b, c) \
    asm("fma.rn.f32x2 %0, %1, %2, %3;" : "=l"(d) : "l"(a), "l"(b), "l"(c))
#define PACK2(d, lo, hi) \
    asm("mov.b64 %0, {%1, %2};" : "=l"(d) : "r"(lo), "r"(hi))
#define UNPACK2(lo, hi, s) \
    asm("mov.b64 {%0, %1}, %2;" : "=r"(lo), "=r"(hi) : "l"(s))

// ---------------------------------------------------------------------------
// Kernel A: camera math -> predicted world points; init mins to +inf
// grid: ((N+127)/128, B), block 128
// ---------------------------------------------------------------------------
__global__ void __launch_bounds__(128)
pred_kernel(const float* __restrict__ c,
            const float* __restrict__ depth,
            int B, int N, int R)
{
    __shared__ float cb[25];
    int b = blockIdx.y;
    if (threadIdx.x < 25) cb[threadIdx.x] = c[b * 25 + threadIdx.x];
    __syncthreads();

    int n = blockIdx.x * blockDim.x + threadIdx.x;
    if (n >= N) return;
    int idx = b * N + n;

    float m00 = cb[0],  m01 = cb[1],  m02 = cb[2],  m03 = cb[3];
    float m10 = cb[4],  m11 = cb[5],  m12 = cb[6],  m13 = cb[7];
    float m20 = cb[8],  m21 = cb[9],  m22 = cb[10], m23 = cb[11];
    float fx  = cb[16], sk = cb[17],  cx  = cb[18];
    float fy  = cb[20], cy = cb[21];

    int i = n / R;
    int j = n - i * R;
    float invR = __fdividef(1.0f, (float)R);
    float x_cam = (j + 0.5f) * invR;
    float y_cam = (i + 0.5f) * invR;

    float invfy = __fdividef(1.0f, fy);
    float invfx = __fdividef(1.0f, fx);
    float x_lift = (x_cam - cx + cy * sk * invfy - sk * y_cam * invfy) * invfx;
    float y_lift = (y_cam - cy) * invfy;

    float wx = m00 * x_lift + m01 * y_lift + m02 + m03;
    float wy = m10 * x_lift + m11 * y_lift + m12 + m13;
    float wz = m20 * x_lift + m21 * y_lift + m22 + m23;

    float ox = m03, oy = m13, oz = m23;
    float dx = wx - ox, dy = wy - oy, dz = wz - oz;
    float invn = rsqrtf(dx * dx + dy * dy + dz * dz);

    float s = depth[idx] * invn;
    float px = fmaf(s, dx, ox);
    float py = fmaf(s, dy, oy);
    float pz = fmaf(s, dz, oz);

    float pn = px * px + py * py + pz * pz;
    g_pred[idx]  = make_float4(px, py, pz, pn);
    g_min_i[idx] = 0x7f800000;  // +inf
}

// ---------------------------------------------------------------------------
// Kernel B: chamfer min sweep, packed f32x2 math.
// d0[n] = pn + min_m (||q||^2 - 2*dot(p,q))
// grid: (M/MCH, N/NTILE, B), block TB
// ---------------------------------------------------------------------------
__global__ void __launch_bounds__(TB)
chamfer_kernel(const float* __restrict__ pc, int B, int N, int M)
{
    // pre-duplicated pc chunk: per m, {(qx,qx),(qy,qy)} and {(qz,qz),(qw,qw)}
    __shared__ ulonglong2 sq[MCH][2];

    int b     = blockIdx.z;
    int ntile = blockIdx.y;
    int m0    = blockIdx.x * MCH;
    int tid   = threadIdx.x;

    const float* pcb = pc + (size_t)b * M * 3;
    for (int m = tid; m < MCH; m += TB) {
        int mg = m0 + m;
        float qx = 0.f, qy = 0.f, qz = 0.f, qw = 1e30f;
        if (mg < M) {
            qx = pcb[mg * 3 + 0];
            qy = pcb[mg * 3 + 1];
            qz = pcb[mg * 3 + 2];
            qw = qx * qx + qy * qy + qz * qz;
        }
        unsigned long long xx, yy, zz, ww;
        unsigned ix = __float_as_uint(qx), iy = __float_as_uint(qy);
        unsigned iz = __float_as_uint(qz), iw = __float_as_uint(qw);
        PACK2(xx, ix, ix); PACK2(yy, iy, iy);
        PACK2(zz, iz, iz); PACK2(ww, iw, iw);
        sq[m][0] = make_ulonglong2(xx, yy);
        sq[m][1] = make_ulonglong2(zz, ww);
    }
    __syncthreads();

    // Register tile: 8 predicted points as 4 packed f32x2 vectors
    unsigned long long px2[NV/2], py2[NV/2], pz2[NV/2];
    float pn[NV], mn[NV];
    int nbase = ntile * NTILE + tid;
    #pragma unroll
    for (int jp = 0; jp < NV/2; jp++) {
        float4 v0 = make_float4(0.f, 0.f, 0.f, 0.f);
        float4 v1 = v0;
        int ng0 = nbase + (2 * jp) * TB;
        int ng1 = nbase + (2 * jp + 1) * TB;
        if (ng0 < N) v0 = g_pred[b * N + ng0];
        if (ng1 < N) v1 = g_pred[b * N + ng1];
        unsigned a, bb;
        a = __float_as_uint(v0.x); bb = __float_as_uint(v1.x); PACK2(px2[jp], a, bb);
        a = __float_as_uint(v0.y); bb = __float_as_uint(v1.y); PACK2(py2[jp], a, bb);
        a = __float_as_uint(v0.z); bb = __float_as_uint(v1.z); PACK2(pz2[jp], a, bb);
        pn[2 * jp]     = v0.w;
        pn[2 * jp + 1] = v1.w;
        mn[2 * jp]     = INFINITY;
        mn[2 * jp + 1] = INFINITY;
    }

    const unsigned long long NEG2 = 0xC0000000C0000000ull;  // (-2.f, -2.f)

    #pragma unroll 4
    for (int m = 0; m < MCH; m++) {
        ulonglong2 qa = sq[m][0];   // (qx,qx),(qy,qy)
        ulonglong2 qb = sq[m][1];   // (qz,qz),(qw,qw)
        #pragma unroll
        for (int jp = 0; jp < NV/2; jp++) {
            unsigned long long dot2, t2;
            F32X2_MUL(dot2, px2[jp], qa.x);
            F32X2_FMA(dot2, py2[jp], qa.y, dot2);
            F32X2_FMA(dot2, pz2[jp], qb.x, dot2);
            F32X2_FMA(t2, NEG2, dot2, qb.y);
            unsigned lo, hi;
            UNPACK2(lo, hi, t2);
            mn[2 * jp]     = fminf(mn[2 * jp],     __uint_as_float(lo));
            mn[2 * jp + 1] = fminf(mn[2 * jp + 1], __uint_as_float(hi));
        }
    }

    #pragma unroll
    for (int k = 0; k < NV; k++) {
        int ng = nbase + k * TB;
        if (ng < N) {
            float v = fmaxf(pn[k] + mn[k], 0.0f);
            atomicMin(&g_min_i[b * N + ng], __float_as_int(v));
        }
    }
}

// ---------------------------------------------------------------------------
// Kernel C: per batch, radix-select the K-th smallest (float bits are
// int-ordered since all >= 0), sum values < tau (+ tie fill), out = 2*mean.
// grid: B blocks of 512 threads
// ---------------------------------------------------------------------------
#define RT 512
__global__ void __launch_bounds__(RT)
reduce_kernel(float* __restrict__ out, int B, int N, int K)
{
    __shared__ unsigned int hist[256];
    __shared__ unsigned int sh_bin, sh_below;
    __shared__ float sred[RT / 32];
    __shared__ unsigned int cred[RT / 32];

    int b   = blockIdx.x;
    int tid = threadIdx.x;
    int VPT = N / RT;  // 8 for N=4096

    unsigned int v[8];
    for (int i = 0; i < VPT; i++)
        v[i] = (unsigned int)g_min_i[b * N + tid + i * RT];

    unsigned int Kr = (unsigned int)K;   // 1-based rank among candidates
    unsigned int prefix = 0, pmask = 0;

    for (int pass = 0; pass < 4; pass++) {
        int shift = 24 - 8 * pass;
        if (tid < 256) hist[tid] = 0;
        __syncthreads();
        for (int i = 0; i < VPT; i++)
            if ((v[i] & pmask) == prefix)
                atomicAdd(&hist[(v[i] >> shift) & 255u], 1u);
        __syncthreads();

        if (tid < 32) {
            unsigned int cs[8], run = 0;
            #pragma unroll
            for (int i = 0; i < 8; i++) { run += hist[tid * 8 + i]; cs[i] = run; }
            unsigned int tot = run;
            // exclusive scan of per-lane totals
            unsigned int x = tot;
            for (int off = 1; off < 32; off <<= 1) {
                unsigned int y = __shfl_up_sync(0xffffffffu, x, off);
                if (tid >= off) x += y;
            }
            unsigned int ex = x - tot;
            bool found = (ex < Kr) && (ex + tot >= Kr);
            if (found) {
                int sel = 0;
                unsigned int below = ex;
                #pragma unroll
                for (int i = 7; i >= 0; i--)
                    if (ex + cs[i] >= Kr) { sel = i; below = ex + (i ? cs[i - 1] : 0u); }
                sh_bin = tid * 8 + sel;
                sh_below = below;
            }
        }
        __syncthreads();
        unsigned int bin = sh_bin;
        Kr -= sh_below;
        prefix |= bin << shift;
        pmask  |= 0xFFu << shift;
        __syncthreads();
    }

    unsigned int tau = prefix;  // exact bits of K-th smallest value

    float sum = 0.0f;
    unsigned int cnt = 0;
    for (int i = 0; i < VPT; i++)
        if (v[i] < tau) { sum += __uint_as_float(v[i]); cnt++; }

    // block reduce (sum, cnt)
    for (int off = 16; off > 0; off >>= 1) {
        sum += __shfl_down_sync(0xffffffffu, sum, off);
        cnt += __shfl_down_sync(0xffffffffu, cnt, off);
    }
    int wid = tid >> 5, lid = tid & 31;
    if (lid == 0) { sred[wid] = sum; cred[wid] = cnt; }
    __syncthreads();
    if (wid == 0) {
        int nw = RT / 32;
        float s = (lid < nw) ? sred[lid] : 0.0f;
        unsigned int c2 = (lid < nw) ? cred[lid] : 0u;
        for (int off = 16; off > 0; off >>= 1) {
            s  += __shfl_down_sync(0xffffffffu, s, off);
            c2 += __shfl_down_sync(0xffffffffu, c2, off);
        }
        if (lid == 0) {
            float rem = (float)((int)K - (int)c2);
            s += rem * __uint_as_float(tau);
            out[b] = 2.0f * s / (float)K;
        }
    }
}

// ---------------------------------------------------------------------------
extern "C" void kernel_launch(void* const* d_in, const int* in_sizes, int n_in,
                              void* d_out, int out_size)
{
    const float* c     = (const float*)d_in[0];
    const float* depth = (const float*)d_in[1];
    const float* pc    = (const float*)d_in[2];

    int B = in_sizes[0] / 25;
    int N = in_sizes[1] / B;
    int M = in_sizes[2] / (B * 3);
    int R = 1;
    while (R * R < N) R++;

    float* out = (float*)d_out;

    dim3 pgrid((N + 127) / 128, B);
    pred_kernel<<<pgrid, 128>>>(c, depth, B, N, R);

    dim3 grid((M + MCH - 1) / MCH, (N + NTILE - 1) / NTILE, B);
    chamfer_kernel<<<grid, TB>>>(pc, B, N, M);

    int K = (N < M ? N : M) / 2;
    reduce_kernel<<<B, RT>>>(out, B, N, K);
}